// round 17
// baseline (speedup 1.0000x reference)
#include <cuda_runtime.h>
#include <math.h>
#include <stdint.h>

// ---------------- problem constants ----------------
#define BB   2
#define SS   1024
#define TKN  2048            // BB*SS tokens
#define HID  1024
#define NH   16
#define NKV  4
#define HD   64
#define NEXP 8
#define TOPK 2
#define II   1024

// ---------------- scratch (device globals; no allocs allowed) ----------------
__device__ float g_xn1  [TKN * HID];
__device__ float g_q    [TKN * NH * HD];
__device__ float g_k    [TKN * NKV * HD];
__device__ float g_v    [TKN * NKV * HD];
__device__ float g_ctx  [TKN * HID];
__device__ float g_resid[TKN * HID];
__device__ float g_x2   [TKN * HID];
__device__ float g_gb   [TKN * II];
__device__ float g_ub   [TKN * II];
__device__ float g_sh   [TKN * HID];
__device__ float g_e1   [NEXP * TKN * II];   // expert gate
__device__ float g_e2   [NEXP * TKN * II];   // expert up
__device__ float g_eo   [NEXP * TKN * HID];  // expert down output
__device__ float g_rprob[TKN * NEXP];
__device__ float g_topv [TKN * TOPK];
__device__ int   g_topi [TKN * TOPK];
__device__ int   g_pos  [TKN * TOPK];
__device__ int   g_cnt  [NEXP];
__device__ int   g_idx  [NEXP * TKN];
__device__ float g_psum [NEXP];
__device__ float g_sgate[TKN];

// ---------------- zero counters ----------------
__global__ void zerocnt_k(int* cnt) {
    if (threadIdx.x < NEXP) cnt[threadIdx.x] = 0;
}

// ---------------- RMSNorm ----------------
__global__ __launch_bounds__(256) void rmsnorm_k(const float* __restrict__ x,
                                                 const float* __restrict__ w,
                                                 float* __restrict__ y) {
    int t = blockIdx.x;
    __shared__ float red[256];
    const float* xr = x + (size_t)t * HID;
    float s = 0.f;
    for (int i = threadIdx.x; i < HID; i += 256) { float v = xr[i]; s += v * v; }
    red[threadIdx.x] = s; __syncthreads();
    for (int st = 128; st > 0; st >>= 1) {
        if (threadIdx.x < st) red[threadIdx.x] += red[threadIdx.x + st];
        __syncthreads();
    }
    float inv = rsqrtf(red[0] / (float)HID + 1e-6f);
    float* yr = y + (size_t)t * HID;
    for (int i = threadIdx.x; i < HID; i += 256) yr[i] = w[i] * xr[i] * inv;
}

// ---------------- mma helpers ----------------
__device__ __forceinline__ void mma8(float* c, const uint32_t* a, const uint32_t* b) {
    asm volatile(
        "mma.sync.aligned.m16n8k8.row.col.f32.tf32.tf32.f32 "
        "{%0,%1,%2,%3}, {%4,%5,%6,%7}, {%8,%9}, {%0,%1,%2,%3};"
        : "+f"(c[0]), "+f"(c[1]), "+f"(c[2]), "+f"(c[3])
        : "r"(a[0]), "r"(a[1]), "r"(a[2]), "r"(a[3]), "r"(b[0]), "r"(b[1]));
}
__device__ __forceinline__ float siluf(float x) {
    return x / (1.f + __expf(-x));
}

#define CP_A16(dst, src) \
    asm volatile("cp.async.cg.shared.global [%0], [%1], 16;\n" :: "r"(dst), "l"(src))
#define CP_COMMIT() asm volatile("cp.async.commit_group;\n" ::)
#define CP_WAIT1()  asm volatile("cp.async.wait_group 1;\n" ::)

// ---------------- GEMM core (tf32 raw-bits, cp.async, 128x256 tile) -------
// 8 warps, each owning a 64x64 warp tile; 1 CTA/SM.
#define BM 128
#define BN 256
#define BK 32
#define STAGES 3
#define ASTR 36     // words/row
#define BSTR 264    // words/row
#define A_ELE (STAGES * BM * ASTR)
#define GSMEM ((STAGES * (BM * ASTR + BK * BSTR)) * 4)

__device__ __forceinline__ void gemm_core(
    const float* __restrict__ A, const float* __restrict__ A2,
    const float* __restrict__ B, float* __restrict__ C,
    int M, int N, int K,
    const int* __restrict__ gidx, const float* __restrict__ addend,
    int row0, int col0, float* sm)
{
    int tid = threadIdx.x, wid = tid >> 5, lane = tid & 31;
    int wm = wid >> 2, wn = wid & 3;          // warp tile 64x64
    int g = lane >> 2, t4 = lane & 3;
    uint32_t sbase = (uint32_t)__cvta_generic_to_shared(sm);

    float acc[4][8][4];
    #pragma unroll
    for (int i = 0; i < 4; i++)
        #pragma unroll
        for (int j = 0; j < 8; j++)
            #pragma unroll
            for (int l = 0; l < 4; l++) acc[i][j][l] = 0.f;

    // A: 4 float4/thread/chunk; B: 8 float4/thread/chunk
    int aRow[4], aCol[4];
    #pragma unroll
    for (int l = 0; l < 4; l++) {
        int f = tid + l * 256;
        aRow[l] = f >> 3;  aCol[l] = (f & 7) * 4;    // 8 float4 per 32-float row
    }
    int bRow[8], bCol[8];
    #pragma unroll
    for (int l = 0; l < 8; l++) {
        int f = tid + l * 256;
        bRow[l] = f >> 6;  bCol[l] = (f & 63) * 4;   // 64 float4 per 256-float row
    }

    int nCh = K / BK;

    auto issue = [&](int kc) {
        if (kc < nCh) {
            int k0 = kc * BK, st = kc % STAGES;
            if (!A2) {
                #pragma unroll
                for (int l = 0; l < 4; l++) {
                    int gr = row0 + aRow[l];
                    if (gr >= M) gr = M - 1;          // clamp: valid addr, row unused
                    int ar = gidx ? gidx[gr] : gr;
                    CP_A16(sbase + (uint32_t)(((st * BM + aRow[l]) * ASTR + aCol[l]) * 4),
                           A + (size_t)ar * K + k0 + aCol[l]);
                }
            } else {
                #pragma unroll
                for (int l = 0; l < 4; l++) {
                    int gr = row0 + aRow[l];
                    int ar = (gr < M) ? gr : (M - 1);
                    size_t off = (size_t)ar * K + k0 + aCol[l];
                    float4 a = *(const float4*)&A[off];
                    float4 u = *(const float4*)&A2[off];
                    a.x = siluf(a.x) * u.x; a.y = siluf(a.y) * u.y;
                    a.z = siluf(a.z) * u.z; a.w = siluf(a.w) * u.w;
                    *(float4*)&sm[(st * BM + aRow[l]) * ASTR + aCol[l]] = a;
                }
            }
            #pragma unroll
            for (int l = 0; l < 8; l++) {
                CP_A16(sbase + (uint32_t)((A_ELE + (st * BK + bRow[l]) * BSTR + bCol[l]) * 4),
                       B + (size_t)(k0 + bRow[l]) * N + col0 + bCol[l]);
            }
        }
        CP_COMMIT();
    };

    issue(0);
    issue(1);

    for (int kc = 0; kc < nCh; kc++) {
        CP_WAIT1();
        __syncthreads();
        issue(kc + 2);
        int cur = kc % STAGES;
        const float* Ab = sm + cur * BM * ASTR;
        const float* Bb = sm + A_ELE + cur * BK * BSTR;
        #pragma unroll
        for (int ks = 0; ks < 4; ks++) {
            int kb = ks * 8;
            uint32_t bf[8][2];
            #pragma unroll
            for (int nt = 0; nt < 8; nt++)
                #pragma unroll
                for (int i = 0; i < 2; i++)
                    bf[nt][i] = __float_as_uint(
                        Bb[(kb + t4 + i * 4) * BSTR + wn * 64 + nt * 8 + g]);
            #pragma unroll
            for (int mt = 0; mt < 4; mt++) {
                uint32_t af[4];
                #pragma unroll
                for (int i = 0; i < 4; i++)
                    af[i] = __float_as_uint(
                        Ab[(wm * 64 + mt * 16 + g + ((i & 1) ? 8 : 0)) * ASTR
                           + kb + t4 + ((i & 2) ? 4 : 0)]);
                #pragma unroll
                for (int nt = 0; nt < 8; nt++)
                    mma8(acc[mt][nt], af, bf[nt]);
            }
        }
    }

    #pragma unroll
    for (int mt = 0; mt < 4; mt++) {
        #pragma unroll
        for (int half = 0; half < 2; half++) {
            int r = row0 + wm * 64 + mt * 16 + g + half * 8;
            if (r >= M) continue;
            #pragma unroll
            for (int nt = 0; nt < 8; nt++) {
                int c = col0 + wn * 64 + nt * 8 + t4 * 2;
                size_t o = (size_t)r * N + c;
                float2 v;
                v.x = acc[mt][nt][half * 2 + 0];
                v.y = acc[mt][nt][half * 2 + 1];
                if (addend) {
                    float2 ad = *(const float2*)&addend[o];
                    v.x += ad.x; v.y += ad.y;
                }
                *(float2*)&C[o] = v;
            }
        }
    }
}

// generic wrapper (per-z strides, gather, dynamic M, addend, fused silu)
__global__ __launch_bounds__(256, 1) void gemm_tc(
    const float* __restrict__ A, const float* __restrict__ A2,
    const float* __restrict__ B,
    float* __restrict__ C, int Mfixed, int N, int K,
    const int* __restrict__ gidx, const int* __restrict__ cntPtr,
    const float* __restrict__ addend,
    size_t Az, size_t Bz, size_t Cz)
{
    extern __shared__ float sm[];
    int ez = blockIdx.z;
    int M = cntPtr ? cntPtr[ez] : Mfixed;
    int row0 = blockIdx.y * BM;
    if (row0 >= M) return;
    A += (size_t)ez * Az; B += (size_t)ez * Bz; C += (size_t)ez * Cz;
    if (A2) A2 += (size_t)ez * Az;
    const int* gi = gidx ? gidx + (size_t)ez * TKN : nullptr;
    gemm_core(A, A2, B, C, M, N, K, gi, addend, row0, blockIdx.x * BN, sm);
}

// fused QKV: grid.x 0-3 -> wq (col x*256), 4 -> wk, 5 -> wv (N=256 each)
__global__ __launch_bounds__(256, 1) void gemm_qkv(
    const float* __restrict__ X,
    const float* __restrict__ wq, const float* __restrict__ wk,
    const float* __restrict__ wv,
    float* __restrict__ q, float* __restrict__ k, float* __restrict__ v)
{
    extern __shared__ float sm[];
    int x = blockIdx.x;
    const float* B; float* C; int N, col0;
    if (x < 4)      { B = wq; C = q; N = NH * HD;  col0 = x * BN; }
    else if (x == 4){ B = wk; C = k; N = NKV * HD; col0 = 0; }
    else            { B = wv; C = v; N = NKV * HD; col0 = 0; }
    gemm_core(X, nullptr, B, C, TKN, N, HID, nullptr, nullptr,
              blockIdx.y * BM, col0, sm);
}

// dual GEMM: same A, two outputs (grid.x split in half)
__global__ __launch_bounds__(256, 1) void gemm_dual(
    const float* __restrict__ A,
    const float* __restrict__ B1, float* __restrict__ C1,
    const float* __restrict__ B2, float* __restrict__ C2,
    int Mfixed, int N, int K,
    const int* __restrict__ gidx, const int* __restrict__ cntPtr,
    size_t Bz, size_t Cz)
{
    extern __shared__ float sm[];
    int ez = blockIdx.z;
    int M = cntPtr ? cntPtr[ez] : Mfixed;
    int row0 = blockIdx.y * BM;
    if (row0 >= M) return;
    int half = gridDim.x >> 1;
    int x = blockIdx.x;
    const float* B = (x < half) ? B1 : B2;
    float* C = (x < half) ? C1 : C2;
    int col0 = ((x < half) ? x : x - half) * BN;
    B += (size_t)ez * Bz; C += (size_t)ez * Cz;
    const int* gi = gidx ? gidx + (size_t)ez * TKN : nullptr;
    gemm_core(A, nullptr, B, C, M, N, K, gi, nullptr, row0, col0, sm);
}

// ---------------- RoPE (in-place on q,k) ----------------
__global__ __launch_bounds__(256) void rope_k(float* __restrict__ Q,
                                              float* __restrict__ Kb,
                                              const int* __restrict__ pos_ids) {
    int t = blockIdx.x;
    float pos = (float)pos_ids[t];
    int tid = threadIdx.x;
    for (int p = tid; p < NH * 32; p += 256) {
        int hh = p >> 5, d = p & 31;
        float invf = powf(1.0e6f, -(float)d / 32.f);
        float s, c; sincosf(pos * invf, &s, &c);
        size_t base = (size_t)t * (NH * HD) + hh * HD;
        float x1 = Q[base + d], x2 = Q[base + d + 32];
        Q[base + d]      = x1 * c - x2 * s;
        Q[base + d + 32] = x2 * c + x1 * s;
    }
    if (tid < NKV * 32) {
        int hh = tid >> 5, d = tid & 31;
        float invf = powf(1.0e6f, -(float)d / 32.f);
        float s, c; sincosf(pos * invf, &s, &c);
        size_t base = (size_t)t * (NKV * HD) + hh * HD;
        float x1 = Kb[base + d], x2 = Kb[base + d + 32];
        Kb[base + d]      = x1 * c - x2 * s;
        Kb[base + d + 32] = x2 * c + x1 * s;
    }
}

// ---------------- tiled causal attention with online softmax --------------
#define TQ  64
#define CKC 32

__global__ __launch_bounds__(256) void attn2_k(const float* __restrict__ Q,
                                               const float* __restrict__ Kb,
                                               const float* __restrict__ Vb,
                                               float* __restrict__ ctx) {
    int qtile = gridDim.x - 1 - blockIdx.x;
    int h = blockIdx.y, b = blockIdx.z;
    int kv = h >> 2;
    __shared__ float Qs[TQ][HD];
    __shared__ float Ks[CKC][68];
    __shared__ float Vs[CKC][HD];
    __shared__ float Ps[TQ][CKC];
    int tid = threadIdx.x, wid = tid >> 5, lane = tid & 31;

    for (int i = tid; i < TQ * HD / 4; i += 256) {
        int r = i >> 4, c4 = i & 15;
        int t = b * SS + qtile * TQ + r;
        ((float4*)Qs[r])[c4] =
            *(const float4*)&Q[(size_t)t * (NH * HD) + h * HD + c4 * 4];
    }

    float m[8], l[8], o0[8], o1[8];
    #pragma unroll
    for (int r = 0; r < 8; r++) { m[r] = -1e30f; l[r] = 0.f; o0[r] = 0.f; o1[r] = 0.f; }
    int row0 = wid * 8;
    int d0 = lane * 2;
    int nch = (qtile + 1) * (TQ / CKC);

    for (int kc = 0; kc < nch; kc++) {
        __syncthreads();
        for (int i = tid; i < CKC * HD / 4; i += 256) {
            int r = i >> 4, c4 = i & 15;
            int t = b * SS + kc * CKC + r;
            size_t base = (size_t)t * (NKV * HD) + kv * HD + c4 * 4;
            *(float4*)&Ks[r][c4 * 4] = *(const float4*)&Kb[base];
            *(float4*)&Vs[r][c4 * 4] = *(const float4*)&Vb[base];
        }
        __syncthreads();
        float s[8];
        #pragma unroll
        for (int r = 0; r < 8; r++) s[r] = 0.f;
        #pragma unroll 4
        for (int d4 = 0; d4 < 16; d4++) {
            float4 k4 = *(const float4*)&Ks[lane][d4 * 4];
            #pragma unroll
            for (int r = 0; r < 8; r++) {
                float4 q4 = ((const float4*)Qs[row0 + r])[d4];
                s[r] += q4.x * k4.x + q4.y * k4.y + q4.z * k4.z + q4.w * k4.w;
            }
        }
        int kpos = kc * CKC + lane;
        #pragma unroll
        for (int r = 0; r < 8; r++) {
            float sv = s[r] * 0.125f;
            int qpos = qtile * TQ + row0 + r;
            if (kpos > qpos) sv = -1e30f;
            float cm = sv;
            #pragma unroll
            for (int off = 16; off; off >>= 1)
                cm = fmaxf(cm, __shfl_xor_sync(0xffffffffu, cm, off));
            float mnew = fmaxf(m[r], cm);
            float p = __expf(sv - mnew);
            float rs = p;
            #pragma unroll
            for (int off = 16; off; off >>= 1)
                rs += __shfl_xor_sync(0xffffffffu, rs, off);
            float alpha = __expf(m[r] - mnew);
            l[r] = l[r] * alpha + rs;
            o0[r] *= alpha; o1[r] *= alpha;
            m[r] = mnew;
            Ps[row0 + r][lane] = p;
        }
        __syncwarp();
        #pragma unroll 4
        for (int kp = 0; kp < CKC / 2; kp++) {
            float2 va = *(const float2*)&Vs[kp * 2][d0];
            float2 vb = *(const float2*)&Vs[kp * 2 + 1][d0];
            #pragma unroll
            for (int r = 0; r < 8; r++) {
                float2 p2 = ((const float2*)Ps[row0 + r])[kp];
                o0[r] += p2.x * va.x + p2.y * vb.x;
                o1[r] += p2.x * va.y + p2.y * vb.y;
            }
        }
    }
    #pragma unroll
    for (int r = 0; r < 8; r++) {
        int t = b * SS + qtile * TQ + row0 + r;
        float inv = 1.f / l[r];
        float2 res = make_float2(o0[r] * inv, o1[r] * inv);
        *(float2*)&ctx[(size_t)t * (NH * HD) + h * HD + d0] = res;
    }
}

// ---------------- router ----------------
__global__ __launch_bounds__(32) void router_k(const float* __restrict__ x2,
                                               const float* __restrict__ rw,
                                               float* __restrict__ rprob,
                                               int* __restrict__ topi,
                                               float* __restrict__ topv) {
    int t = blockIdx.x, lane = threadIdx.x;
    float part[NEXP] = {};
    const float* xr = x2 + (size_t)t * HID;
    for (int k = lane; k < HID; k += 32) {
        float xv = xr[k];
        #pragma unroll
        for (int e = 0; e < NEXP; e++) part[e] += xv * rw[k * NEXP + e];
    }
    #pragma unroll
    for (int e = 0; e < NEXP; e++)
        for (int off = 16; off; off >>= 1)
            part[e] += __shfl_xor_sync(0xffffffff, part[e], off);
    if (lane == 0) {
        float m = part[0];
        #pragma unroll
        for (int e = 1; e < NEXP; e++) m = fmaxf(m, part[e]);
        float p[NEXP], s = 0.f;
        #pragma unroll
        for (int e = 0; e < NEXP; e++) { p[e] = expf(part[e] - m); s += p[e]; }
        #pragma unroll
        for (int e = 0; e < NEXP; e++) { p[e] /= s; rprob[t * NEXP + e] = p[e]; }
        int i1 = 0; float v1 = p[0];
        for (int e = 1; e < NEXP; e++) if (p[e] > v1) { v1 = p[e]; i1 = e; }
        int i2 = -1; float v2 = -1.f;
        for (int e = 0; e < NEXP; e++) if (e != i1 && p[e] > v2) { v2 = p[e]; i2 = e; }
        topi[t * 2]     = i1; topv[t * 2]     = v1;
        topi[t * 2 + 1] = i2; topv[t * 2 + 1] = v2;
    }
}

// deterministic per-expert prob sum (for aux)
__global__ __launch_bounds__(256) void psum_k(const float* __restrict__ rprob,
                                              float* __restrict__ psum) {
    int e = blockIdx.x;
    __shared__ float red[256];
    float s = 0.f;
    for (int t = threadIdx.x; t < TKN; t += 256) s += rprob[t * NEXP + e];
    red[threadIdx.x] = s; __syncthreads();
    for (int st = 128; st > 0; st >>= 1) {
        if (threadIdx.x < st) red[threadIdx.x] += red[threadIdx.x + st];
        __syncthreads();
    }
    if (threadIdx.x == 0) psum[e] = red[0];
}

// build per-expert token lists (records position for later gather)
__global__ void scatter_k(const int* __restrict__ topi,
                          int* cnt, int* idx, int* posArr) {
    int t = blockIdx.x * 256 + threadIdx.x;
    if (t >= TKN) return;
    for (int j = 0; j < TOPK; j++) {
        int e = topi[t * 2 + j];
        int pos = atomicAdd(&cnt[e], 1);
        idx[e * TKN + pos] = t;
        posArr[t * 2 + j] = pos;
    }
}

// shared-expert sigmoid gate
__global__ __launch_bounds__(32) void sgate_k(const float* __restrict__ x2,
                                              const float* __restrict__ seg,
                                              float* __restrict__ sgate) {
    int t = blockIdx.x, lane = threadIdx.x;
    const float* xr = x2 + (size_t)t * HID;
    float s = 0.f;
    for (int k = lane; k < HID; k += 32) s += xr[k] * seg[k];
    for (int off = 16; off; off >>= 1) s += __shfl_xor_sync(0xffffffff, s, off);
    if (lane == 0) sgate[t] = 1.f / (1.f + expf(-s));
}

// out = resid + sum_j topv*expert_down[j] + sgate * shared
__global__ void final_k(const float* __restrict__ resid,
                        const float* __restrict__ yb,
                        const int* __restrict__ topi, const float* __restrict__ topv,
                        const int* __restrict__ posArr,
                        const float* __restrict__ sh, const float* __restrict__ sgate,
                        float* __restrict__ out, int n) {
    int i = blockIdx.x * 256 + threadIdx.x;
    if (i >= n) return;
    int t = i >> 10;
    int col = i & 1023;
    float moe = 0.f;
    #pragma unroll
    for (int j = 0; j < TOPK; j++) {
        int e = topi[t * 2 + j];
        int p = posArr[t * 2 + j];
        moe += topv[t * 2 + j] * yb[((size_t)e * TKN + p) * HID + col];
    }
    out[i] = resid[i] + moe + sgate[t] * sh[i];
}

__global__ void aux_k(const float* __restrict__ psum, float* __restrict__ out,
                      int doWrite, int pos) {
    if (threadIdx.x == 0 && doWrite) {
        float a = 0.f;
        for (int e = 0; e < NEXP; e++) {
            float d = psum[e] / (float)TKN - 1.f / (float)NEXP;
            a += d * d;
        }
        out[pos] = a / (float)NEXP;
    }
}

// ---------------- launch ----------------
extern "C" void kernel_launch(void* const* d_in, const int* in_sizes, int n_in,
                              void* d_out, int out_size) {
    const float* hidden = (const float*)d_in[0];
    const int*   pos  = (const int*)  d_in[2];
    const float* ln1  = (const float*)d_in[3];
    const float* ln2  = (const float*)d_in[4];
    const float* wq   = (const float*)d_in[5];
    const float* wk   = (const float*)d_in[6];
    const float* wv   = (const float*)d_in[7];
    const float* wo   = (const float*)d_in[8];
    const float* rw   = (const float*)d_in[9];
    const float* egw  = (const float*)d_in[10];
    const float* euw  = (const float*)d_in[11];
    const float* edw  = (const float*)d_in[12];
    const float* sgw  = (const float*)d_in[13];
    const float* suw  = (const float*)d_in[14];
    const float* sdw  = (const float*)d_in[15];
    const float* segw = (const float*)d_in[16];
    float* out = (float*)d_out;

    float *xn1, *q, *k, *v, *ctx, *resid, *x2, *gb, *ub, *sh, *e1, *e2, *eo;
    float *rprob, *topv, *psum, *sgate;
    int *topi, *cnt, *idx, *posArr;
    cudaGetSymbolAddress((void**)&xn1,   g_xn1);
    cudaGetSymbolAddress((void**)&q,     g_q);
    cudaGetSymbolAddress((void**)&k,     g_k);
    cudaGetSymbolAddress((void**)&v,     g_v);
    cudaGetSymbolAddress((void**)&ctx,   g_ctx);
    cudaGetSymbolAddress((void**)&resid, g_resid);
    cudaGetSymbolAddress((void**)&x2,    g_x2);
    cudaGetSymbolAddress((void**)&gb,    g_gb);
    cudaGetSymbolAddress((void**)&ub,    g_ub);
    cudaGetSymbolAddress((void**)&sh,    g_sh);
    cudaGetSymbolAddress((void**)&e1,    g_e1);
    cudaGetSymbolAddress((void**)&e2,    g_e2);
    cudaGetSymbolAddress((void**)&eo,    g_eo);
    cudaGetSymbolAddress((void**)&rprob, g_rprob);
    cudaGetSymbolAddress((void**)&topv,  g_topv);
    cudaGetSymbolAddress((void**)&topi,  g_topi);
    cudaGetSymbolAddress((void**)&posArr,g_pos);
    cudaGetSymbolAddress((void**)&cnt,   g_cnt);
    cudaGetSymbolAddress((void**)&idx,   g_idx);
    cudaGetSymbolAddress((void**)&psum,  g_psum);
    cudaGetSymbolAddress((void**)&sgate, g_sgate);

    // streams/events/attributes set up once, outside graph capture
    static cudaStream_t s1 = nullptr, s2 = nullptr;
    static cudaEvent_t ev[8];
    if (!s1) {
        cudaStreamCreateWithFlags(&s1, cudaStreamNonBlocking);
        cudaStreamCreateWithFlags(&s2, cudaStreamNonBlocking);
        for (int i = 0; i < 8; i++)
            cudaEventCreateWithFlags(&ev[i], cudaEventDisableTiming);
        cudaFuncSetAttribute(gemm_tc,  cudaFuncAttributeMaxDynamicSharedMemorySize, GSMEM);
        cudaFuncSetAttribute(gemm_qkv, cudaFuncAttributeMaxDynamicSharedMemorySize, GSMEM);
        cudaFuncSetAttribute(gemm_dual,cudaFuncAttributeMaxDynamicSharedMemorySize, GSMEM);
    }
    cudaStream_t s0 = 0;

    dim3 gFull(HID / BN, TKN / BM, 1);          // 4 x 16
    dim3 gQKV(6, TKN / BM, 1);                  // 6 x 16 (4 q + 1 k + 1 v)
    dim3 gDualSh(2 * II / BN, TKN / BM, 1);     // 8 x 16
    dim3 gDualEx(2 * II / BN, TKN / BM, NEXP);  // 8 x 16 x 8
    dim3 gExpDown(HID / BN, TKN / BM, NEXP);    // 4 x 16 x 8

    zerocnt_k<<<1, 32, 0, s0>>>(cnt);

    // attention branch
    rmsnorm_k<<<TKN, 256, 0, s0>>>(hidden, ln1, xn1);
    gemm_qkv<<<gQKV, 256, GSMEM, s0>>>(xn1, wq, wk, wv, q, k, v);
    rope_k<<<TKN, 256, 0, s0>>>(q, k, pos);
    dim3 gAttn(SS / TQ, NH, BB);
    attn2_k<<<gAttn, 256, 0, s0>>>(q, k, v, ctx);
    gemm_tc<<<gFull, 256, GSMEM, s0>>>(ctx, nullptr, wo, resid, TKN, HID, NH * HD,
                                       nullptr, nullptr, hidden, 0, 0, 0);

    // MoE branch
    rmsnorm_k<<<TKN, 256, 0, s0>>>(resid, ln2, x2);

    // fork shared-expert chain onto s1, sgate onto s2
    cudaEventRecord(ev[3], s0);
    cudaStreamWaitEvent(s1, ev[3], 0);
    cudaStreamWaitEvent(s2, ev[3], 0);
    gemm_dual<<<gDualSh, 256, GSMEM, s1>>>(x2, sgw, gb, suw, ub, TKN, II, HID,
                                           nullptr, nullptr, 0, 0);
    gemm_tc<<<gFull, 256, GSMEM, s1>>>(gb, ub, sdw, sh, TKN, HID, II,
                                       nullptr, nullptr, nullptr, 0, 0, 0);
    sgate_k<<<TKN, 32, 0, s2>>>(x2, segw, sgate);

    // routed chain on s0
    router_k<<<TKN, 32, 0, s0>>>(x2, rw, rprob, topi, topv);
    psum_k<<<NEXP, 256, 0, s0>>>(rprob, psum);
    scatter_k<<<(TKN + 255) / 256, 256, 0, s0>>>(topi, cnt, idx, posArr);
    gemm_dual<<<gDualEx, 256, GSMEM, s0>>>(x2, egw, e1, euw, e2, TKN, II, HID,
                                           idx, cnt, (size_t)HID * II,
                                           (size_t)TKN * II);
    gemm_tc<<<gExpDown, 256, GSMEM, s0>>>(e1, e2, edw, eo, TKN, HID, II,
                                          nullptr, cnt, nullptr,
                                          (size_t)TKN * II, (size_t)II * HID,
                                          (size_t)TKN * HID);

    // join shared chain + sgate
    cudaEventRecord(ev[5], s1);
    cudaStreamWaitEvent(s0, ev[5], 0);
    cudaEventRecord(ev[6], s2);
    cudaStreamWaitEvent(s0, ev[6], 0);

    // combine
    int n = TKN * HID;
    int ncopy = out_size < n ? out_size : n;
    final_k<<<(n + 255) / 256, 256, 0, s0>>>(resid, eo, topi, topv, posArr,
                                             sh, sgate, out, ncopy);
    aux_k<<<1, 32, 0, s0>>>(psum, out, out_size > n ? 1 : 0, n);
}